// round 15
// baseline (speedup 1.0000x reference)
#include <cuda_runtime.h>
#include <cuda_bf16.h>
#include <math.h>
#include <stdint.h>
#include <stddef.h>

#define TSTEPS 1024
#define BATCH  128
#define INDIM  512
#define HID    512
#define GATES  2048   // gate order: i, f, o, g
#define NBLK   64     // recurrence blocks (fat: 8 hidden each)

// ---------------------------------------------------------------------------
// Device-global scratch
// ---------------------------------------------------------------------------
__device__ float g_xprojT[(size_t)TSTEPS * GATES * BATCH];     // [t][gate][b]
__device__ __nv_bfloat16 g_hhi[2][HID * BATCH];                // h split, [k][b], dbl-buffered
__device__ __nv_bfloat16 g_hlo[2][HID * BATCH];
__device__ __nv_bfloat16 g_xhi[(size_t)TSTEPS * BATCH * INDIM];
__device__ __nv_bfloat16 g_xlo[(size_t)TSTEPS * BATCH * INDIM];
__device__ __nv_bfloat16 g_whi[(size_t)GATES * INDIM];
__device__ __nv_bfloat16 g_wlo[(size_t)GATES * INDIM];
__device__ unsigned g_count;       // init barrier (atomic, self-resetting)
__device__ unsigned g_gen;
__device__ __align__(16) unsigned g_flags[128]; // step barrier flags (monotonic)
__device__ unsigned g_genv;        // step barrier release word (monotonic)

// classic full barrier (used once after init; self-resetting)
__device__ __forceinline__ void grid_barrier(unsigned nb) {
    __syncthreads();
    if (threadIdx.x == 0) {
        unsigned my = *(volatile unsigned*)&g_gen;
        __threadfence();
        unsigned old = atomicAdd(&g_count, 1u);
        if (old == nb - 1u) {
            atomicExch(&g_count, 0u);
            __threadfence();
            atomicAdd(&g_gen, 1u);
        } else {
            while (*(volatile unsigned*)&g_gen == my) { }
        }
        __threadfence();
    }
    __syncthreads();
}

__device__ __forceinline__ uint32_t smem_u32(const void* p) {
    uint32_t a;
    asm("{ .reg .u64 t; cvta.to.shared.u64 t, %1; cvt.u32.u64 %0, t; }"
        : "=r"(a) : "l"(p));
    return a;
}
#define CP16(dst, src) \
    asm volatile("cp.async.cg.shared.global [%0], [%1], 16;" \
                 :: "r"(dst), "l"(src) : "memory")
#define CP_COMMIT() asm volatile("cp.async.commit_group;" ::: "memory")
#define CP_WAIT(n)  asm volatile("cp.async.wait_group %0;" :: "n"(n) : "memory")

__device__ __forceinline__ void ldm4(uint32_t* r, uint32_t addr) {
    asm volatile("ldmatrix.sync.aligned.m8n8.x4.shared.b16 {%0,%1,%2,%3}, [%4];"
        : "=r"(r[0]), "=r"(r[1]), "=r"(r[2]), "=r"(r[3]) : "r"(addr));
}
__device__ __forceinline__ void ldm4t(uint32_t* r, uint32_t addr) {
    asm volatile("ldmatrix.sync.aligned.m8n8.x4.trans.shared.b16 {%0,%1,%2,%3}, [%4];"
        : "=r"(r[0]), "=r"(r[1]), "=r"(r[2]), "=r"(r[3]) : "r"(addr));
}
__device__ __forceinline__ void mma_bf16(float* c, const uint32_t* a, const uint32_t* b) {
    asm volatile("mma.sync.aligned.m16n8k16.row.col.f32.bf16.bf16.f32 "
        "{%0,%1,%2,%3}, {%4,%5,%6,%7}, {%8,%9}, {%0,%1,%2,%3};"
        : "+f"(c[0]), "+f"(c[1]), "+f"(c[2]), "+f"(c[3])
        : "r"(a[0]), "r"(a[1]), "r"(a[2]), "r"(a[3]), "r"(b[0]), "r"(b[1]));
}

// ---------------------------------------------------------------------------
// Phase 0: split fp32 -> bf16 (hi, lo)
// ---------------------------------------------------------------------------
__global__ void split_x_kernel(const float* __restrict__ src) {
    const int n4 = (TSTEPS * BATCH * INDIM) / 4;
    for (int i = blockIdx.x * blockDim.x + threadIdx.x; i < n4;
         i += gridDim.x * blockDim.x) {
        float4 v = ((const float4*)src)[i];
        __nv_bfloat16 hx = __float2bfloat16(v.x), hy = __float2bfloat16(v.y);
        __nv_bfloat16 hz = __float2bfloat16(v.z), hw = __float2bfloat16(v.w);
        __nv_bfloat162* H = (__nv_bfloat162*)(g_xhi + (size_t)i * 4);
        H[0] = __nv_bfloat162(hx, hy); H[1] = __nv_bfloat162(hz, hw);
        __nv_bfloat162* L = (__nv_bfloat162*)(g_xlo + (size_t)i * 4);
        L[0] = __nv_bfloat162(__float2bfloat16(v.x - __bfloat162float(hx)),
                              __float2bfloat16(v.y - __bfloat162float(hy)));
        L[1] = __nv_bfloat162(__float2bfloat16(v.z - __bfloat162float(hz)),
                              __float2bfloat16(v.w - __bfloat162float(hw)));
    }
}
__global__ void split_w_kernel(const float* __restrict__ src) {
    const int n4 = (GATES * INDIM) / 4;
    for (int i = blockIdx.x * blockDim.x + threadIdx.x; i < n4;
         i += gridDim.x * blockDim.x) {
        float4 v = ((const float4*)src)[i];
        __nv_bfloat16 hx = __float2bfloat16(v.x), hy = __float2bfloat16(v.y);
        __nv_bfloat16 hz = __float2bfloat16(v.z), hw = __float2bfloat16(v.w);
        __nv_bfloat162* H = (__nv_bfloat162*)(g_whi + (size_t)i * 4);
        H[0] = __nv_bfloat162(hx, hy); H[1] = __nv_bfloat162(hz, hw);
        __nv_bfloat162* L = (__nv_bfloat162*)(g_wlo + (size_t)i * 4);
        L[0] = __nv_bfloat162(__float2bfloat16(v.x - __bfloat162float(hx)),
                              __float2bfloat16(v.y - __bfloat162float(hy)));
        L[1] = __nv_bfloat162(__float2bfloat16(v.z - __bfloat162float(hz)),
                              __float2bfloat16(v.w - __bfloat162float(hw)));
    }
}

// ---------------------------------------------------------------------------
// Phase 1: xproj GEMM via mma.sync bf16 3-split (R9 version: proven).
// ---------------------------------------------------------------------------
#define XB_BUF    1024
#define XB_STAGE  40960
#define XB_AH     0
#define XB_AL     10240
#define XB_BH     20480
#define XB_BL     30720
#define SMEM_XP   (XB_BUF + 2 * XB_STAGE)

__global__ __launch_bounds__(256) void xproj_mma_kernel(
    const float* __restrict__ bih, const float* __restrict__ bhh)
{
    extern __shared__ char sm[];
    const uint32_t smb = smem_u32(sm);
    float* bias = (float*)sm;
    const int tid = threadIdx.x, wid = tid >> 5, lane = tid & 31;
    const int mw = wid & 1, nw = wid >> 1;
    const int t = blockIdx.y;
    const int n0 = blockIdx.x * 128;

    if (tid < 128) bias[tid] = bih[n0 + tid] + bhh[n0 + tid];

    float acc[4][4][4];
#pragma unroll
    for (int a = 0; a < 4; a++)
#pragma unroll
        for (int b = 0; b < 4; b++)
#pragma unroll
            for (int q = 0; q < 4; q++) acc[a][b][q] = 0.f;

    const int arow = ((lane >> 3) & 1) * 8 + (lane & 7);
    const int ach  = lane >> 4;
    const int brow = ((lane >> 4) & 1) * 8 + (lane & 7);
    const int bch  = (lane >> 3) & 1;

#define XP_ISSUE(s_, c_) do {                                                  \
    _Pragma("unroll")                                                          \
    for (int j_ = 0; j_ < 2; j_++) {                                           \
        const int u_ = j_ * 256 + tid;                                         \
        const int r_ = u_ >> 2, cc_ = u_ & 3;                                  \
        const size_t gx_ = ((size_t)t * 128 + r_) * INDIM + (c_) * 32 + cc_ * 8; \
        const size_t gw_ = (size_t)(n0 + r_) * INDIM + (c_) * 32 + cc_ * 8;    \
        const uint32_t db_ = smb + XB_BUF + (s_) * XB_STAGE + r_ * 80 + cc_ * 16; \
        CP16(db_ + XB_AH, g_xhi + gx_);                                        \
        CP16(db_ + XB_AL, g_xlo + gx_);                                        \
        CP16(db_ + XB_BH, g_whi + gw_);                                        \
        CP16(db_ + XB_BL, g_wlo + gw_);                                        \
    }                                                                          \
    CP_COMMIT();                                                               \
} while (0)

    XP_ISSUE(0, 0);
#pragma unroll 1
    for (int c = 0; c < 16; c++) {
        if (c < 15) { XP_ISSUE((c + 1) & 1, c + 1); CP_WAIT(1); }
        else        { CP_WAIT(0); }
        __syncthreads();
        const uint32_t base = smb + XB_BUF + (c & 1) * XB_STAGE;
#pragma unroll
        for (int h = 0; h < 2; h++) {
            uint32_t ah[4][4], al[4][4], bhf[2][4], blf[2][4];
#pragma unroll
            for (int mt = 0; mt < 4; mt++) {
                const uint32_t aA = base + XB_AH +
                    (uint32_t)(mw * 64 + mt * 16 + arow) * 80 + (h * 2 + ach) * 16;
                ldm4(ah[mt], aA);
                ldm4(al[mt], aA + (XB_AL - XB_AH));
            }
#pragma unroll
            for (int bt = 0; bt < 2; bt++) {
                const uint32_t aB = base + XB_BH +
                    (uint32_t)(nw * 32 + bt * 16 + brow) * 80 + (h * 2 + bch) * 16;
                ldm4(bhf[bt], aB);
                ldm4(blf[bt], aB + (XB_BL - XB_BH));
            }
#pragma unroll
            for (int mt = 0; mt < 4; mt++)
#pragma unroll
                for (int bt = 0; bt < 2; bt++) {
                    mma_bf16(acc[mt][bt * 2 + 0], ah[mt], bhf[bt] + 0);
                    mma_bf16(acc[mt][bt * 2 + 1], ah[mt], bhf[bt] + 2);
                    mma_bf16(acc[mt][bt * 2 + 0], ah[mt], blf[bt] + 0);
                    mma_bf16(acc[mt][bt * 2 + 1], ah[mt], blf[bt] + 2);
                    mma_bf16(acc[mt][bt * 2 + 0], al[mt], bhf[bt] + 0);
                    mma_bf16(acc[mt][bt * 2 + 1], al[mt], bhf[bt] + 2);
                }
        }
        __syncthreads();
    }

    float* ep = (float*)(sm + XB_BUF);
    const int g = lane >> 2, tg2 = (lane & 3) * 2;
#pragma unroll
    for (int mt = 0; mt < 4; mt++)
#pragma unroll
        for (int nt = 0; nt < 4; nt++) {
            const int bb = mw * 64 + mt * 16 + g;
            const int nn = nw * 32 + nt * 8 + tg2;
            ep[(nn)     * 132 + bb]     = acc[mt][nt][0] + bias[nn];
            ep[(nn + 1) * 132 + bb]     = acc[mt][nt][1] + bias[nn + 1];
            ep[(nn)     * 132 + bb + 8] = acc[mt][nt][2] + bias[nn];
            ep[(nn + 1) * 132 + bb + 8] = acc[mt][nt][3] + bias[nn + 1];
        }
    __syncthreads();
#pragma unroll
    for (int j = 0; j < 16; j++) {
        const int idx = j * 256 + tid;
        const int n = idx >> 5, q = idx & 31;
        const float4 v = *(const float4*)(ep + n * 132 + q * 4);
        *(float4*)(g_xprojT + ((size_t)t * GATES + n0 + n) * BATCH + q * 4) = v;
    }
}

// ---------------------------------------------------------------------------
// Phase 2: persistent recurrence — 64 fat blocks (M=32: 8 hidden/block),
// combining R5's M=32 ownership with R6/R9's proven pipeline:
//   - kq-PARITY-split accumulators (8 independent HMMA chains — fixes R5's
//     serial-chain regression),
//   - 4-buffer 64-row cp.async pipeline, R9 sync schedule,
//   - R9 flag-tree barrier (64 participants now).
// Halves the per-step h broadcast (16 MB/step) and barrier arrivals.
// ---------------------------------------------------------------------------
#define R14_WHI   0                        // 32 rows x 520 halves (1040B)
#define R14_WLO   33280
#define R14_HBUF  66560                    // 4 bufs x (hi 64x272 | lo 64x272)
#define R14_HB(b_) (R14_HBUF + (b_) * 34816)
#define R14_ZS    205824                   // fp32 [32][132]
#define R14_HSTG  222720                   // fp32 [8][128]
#define SMEM_REC14 226816

__global__ __launch_bounds__(256) void rec14_kernel(
    const float* __restrict__ Whh, float* __restrict__ out)
{
    extern __shared__ char sm[];
    const uint32_t smb = smem_u32(sm);
    float* zs   = (float*)(sm + R14_ZS);
    float* hstg = (float*)(sm + R14_HSTG);

    const int tid = threadIdx.x, bid = blockIdx.x;
    const int wid = tid >> 5, lane = tid & 31;
    const int j0 = bid << 3;
    const int n0 = wid << 4;

    // W_hh slice -> SMEM bf16 hi/lo, row m = gt*8+u, stride 520 halves
    for (int i = tid; i < 32 * 512; i += 256) {
        const int m = i >> 9, k = i & 511;
        const int gr = (m >> 3) * 512 + j0 + (m & 7);
        const float w = Whh[(size_t)gr * HID + k];
        const __nv_bfloat16 wh = __float2bfloat16(w);
        ((__nv_bfloat16*)(sm + R14_WHI))[m * 520 + k] = wh;
        ((__nv_bfloat16*)(sm + R14_WLO))[m * 520 + k] =
            __float2bfloat16(w - __bfloat162float(wh));
    }
    // zero h buffer 0; reset step-barrier state
    for (int i = bid * 256 + tid; i < 32768; i += NBLK * 256) {
        ((uint32_t*)g_hhi[0])[i] = 0u;
        ((uint32_t*)g_hlo[0])[i] = 0u;
    }
    if (bid == 0) {
        if (tid < NBLK) g_flags[tid] = 0u;
        if (tid == 0)   *(volatile unsigned*)&g_genv = 0u;
    }
    __threadfence();
    grid_barrier(NBLK);

    // lane addressing
    const int arow = ((lane >> 3) & 1) * 8 + (lane & 7);
    const int ach  = lane >> 4;
    const uint32_t aoff0 = smb + R14_WHI + (uint32_t)arow * 1040 + ach * 16;
    const uint32_t aoff1 = aoff0 + 16 * 1040;
    const int krow = ((lane >> 3) & 1) * 8 + (lane & 7);
    const uint32_t bcoloff = (uint32_t)(n0 + (lane >> 4) * 8) * 2;
    const int drow = lane >> 2, dcol = (lane & 3) * 2;

    const int b_ = tid & 127, ug = (tid >> 7) * 4;
    float creg[4] = {0.f, 0.f, 0.f, 0.f}, hreg[4] = {0.f, 0.f, 0.f, 0.f};

#define REC_ISSUE(c_, bb_) do {                                                \
    _Pragma("unroll")                                                          \
    for (int j_ = 0; j_ < 4; j_++) {                                           \
        const int u_ = j_ * 256 + tid;                                         \
        const int r_ = u_ >> 4, cc_ = u_ & 15;                                 \
        const uint32_t d_ = smb + R14_HB(bb_) + r_ * 272 + cc_ * 16;           \
        const size_t s_ = hoff + ((size_t)(c_) * 64 + r_) * 128 + cc_ * 8;     \
        CP16(d_, g_hhi[0] + s_);                                               \
        CP16(d_ + 17408, g_hlo[0] + s_);                                       \
    }                                                                          \
    CP_COMMIT();                                                               \
} while (0)

    // acc[par][mt][nt][4]: par = kq&1 (independent chains), persistent par0
    float acc0[2][2][4];   // par 0 — initialized from xproj
    float acc1[2][2][4];   // par 1 — zeroed per step

    // prefetch xproj for t=0 into acc0
#define LOAD_XP32(t_) do {                                                     \
    _Pragma("unroll")                                                          \
    for (int mt = 0; mt < 2; mt++) {                                           \
        const int mlo = mt * 16 + drow, mhi = mlo + 8;                         \
        const float* plo = g_xprojT +                                          \
            ((size_t)(t_) * GATES + (mlo >> 3) * 512 + j0 + (mlo & 7)) * BATCH \
            + n0 + dcol;                                                       \
        const float* phi = g_xprojT +                                          \
            ((size_t)(t_) * GATES + (mhi >> 3) * 512 + j0 + (mhi & 7)) * BATCH \
            + n0 + dcol;                                                       \
        float2 v_;                                                             \
        v_ = *(const float2*)(plo);     acc0[mt][0][0] = v_.x; acc0[mt][0][1] = v_.y; \
        v_ = *(const float2*)(phi);     acc0[mt][0][2] = v_.x; acc0[mt][0][3] = v_.y; \
        v_ = *(const float2*)(plo + 8); acc0[mt][1][0] = v_.x; acc0[mt][1][1] = v_.y; \
        v_ = *(const float2*)(phi + 8); acc0[mt][1][2] = v_.x; acc0[mt][1][3] = v_.y; \
    }                                                                          \
} while (0)

    LOAD_XP32(0);

    for (int t = 0; t < TSTEPS; t++) {
        const size_t hoff = (size_t)(t & 1) * (HID * BATCH);

#pragma unroll
        for (int mt = 0; mt < 2; mt++)
#pragma unroll
            for (int nt = 0; nt < 2; nt++)
#pragma unroll
                for (int q = 0; q < 4; q++) acc1[mt][nt][q] = 0.f;

        REC_ISSUE(0, 0);
        REC_ISSUE(1, 1);
        REC_ISSUE(2, 2);
        REC_ISSUE(3, 3);

#pragma unroll 1
        for (int c = 0; c < 8; c++) {
            const int bb = c & 3;
            if (c < 5)      CP_WAIT(3);
            else if (c == 5) CP_WAIT(2);
            else if (c == 6) CP_WAIT(1);
            else             CP_WAIT(0);
            __syncthreads();
#pragma unroll
            for (int kq = 0; kq < 4; kq++) {
                const int k16 = c * 4 + kq;
                uint32_t ahi0[4], alo0[4], ahi1[4], alo1[4], bhi[4], blo[4];
                ldm4(ahi0, aoff0 + k16 * 32);
                ldm4(alo0, aoff0 + k16 * 32 + (R14_WLO - R14_WHI));
                ldm4(ahi1, aoff1 + k16 * 32);
                ldm4(alo1, aoff1 + k16 * 32 + (R14_WLO - R14_WHI));
                const uint32_t ba = smb + R14_HB(bb)
                    + (uint32_t)(kq * 16 + krow) * 272 + bcoloff;
                ldm4t(bhi, ba);
                ldm4t(blo, ba + 17408);
                float (*ax)[2][4] = (kq & 1) ? acc1 : acc0;
                mma_bf16(ax[0][0], ahi0, bhi + 0);
                mma_bf16(ax[0][1], ahi0, bhi + 2);
                mma_bf16(ax[1][0], ahi1, bhi + 0);
                mma_bf16(ax[1][1], ahi1, bhi + 2);
                mma_bf16(ax[0][0], ahi0, blo + 0);
                mma_bf16(ax[0][1], ahi0, blo + 2);
                mma_bf16(ax[1][0], ahi1, blo + 0);
                mma_bf16(ax[1][1], ahi1, blo + 2);
                mma_bf16(ax[0][0], alo0, bhi + 0);
                mma_bf16(ax[0][1], alo0, bhi + 2);
                mma_bf16(ax[1][0], alo1, bhi + 0);
                mma_bf16(ax[1][1], alo1, bhi + 2);
            }
            __syncthreads();
            if (c < 4) REC_ISSUE(c + 4, bb);
        }

        // merge parity sets; z fragments -> SMEM [m][b]
#pragma unroll
        for (int mt = 0; mt < 2; mt++) {
#pragma unroll
            for (int nt = 0; nt < 2; nt++)
#pragma unroll
                for (int q = 0; q < 4; q++) acc0[mt][nt][q] += acc1[mt][nt][q];
            const int nc = n0 + dcol;
            float* zlo = zs + (mt * 16 + drow) * 132;
            float* zhi = zs + (mt * 16 + drow + 8) * 132;
            *(float2*)&zlo[nc]     = make_float2(acc0[mt][0][0], acc0[mt][0][1]);
            *(float2*)&zhi[nc]     = make_float2(acc0[mt][0][2], acc0[mt][0][3]);
            *(float2*)&zlo[nc + 8] = make_float2(acc0[mt][1][0], acc0[mt][1][1]);
            *(float2*)&zhi[nc + 8] = make_float2(acc0[mt][1][2], acc0[mt][1][3]);
        }
        __syncthreads();

        // gates: thread handles u = ug..ug+3, batch b_; publish parity (t+1)&1
        {
            __nv_bfloat16* dst_hi = g_hhi[(t + 1) & 1];
            __nv_bfloat16* dst_lo = g_hlo[(t + 1) & 1];
#pragma unroll
            for (int q = 0; q < 4; q++) {
                const int u = ug + q;
                const float zi = zs[( 0 + u) * 132 + b_];
                const float zf = zs[( 8 + u) * 132 + b_];
                const float zo = zs[(16 + u) * 132 + b_];
                const float zg = zs[(24 + u) * 132 + b_];
                const float ig = 1.f / (1.f + expf(-zi));
                const float fg = 1.f / (1.f + expf(-zf));
                const float og = 1.f / (1.f + expf(-zo));
                const float gg = tanhf(zg);
                const float cc = fg * creg[q] + ig * gg;
                creg[q] = cc;
                const float h = og * tanhf(cc);
                hreg[q] = h;
                hstg[u * 128 + b_] = h;
                const __nv_bfloat16 hh = __float2bfloat16(h);
                dst_hi[(j0 + u) * BATCH + b_] = hh;
                dst_lo[(j0 + u) * BATCH + b_] =
                    __float2bfloat16(h - __bfloat162float(hh));
            }
        }
        __syncthreads();          // hstg + all publishes done block-wide

        // ---- flag-tree split barrier: arrive ----
        if (tid == 0) {
            __threadfence();
            *(volatile unsigned*)&g_flags[bid] = (unsigned)(t + 1);
        }

        // overlap window: out-store + next-step xproj prefetch
        if (tid < 128) {
            float* dst = out + ((size_t)t * BATCH + tid) * HID + j0;
            *(float4*)(dst)     = make_float4(hstg[0 * 128 + tid], hstg[1 * 128 + tid],
                                              hstg[2 * 128 + tid], hstg[3 * 128 + tid]);
            *(float4*)(dst + 4) = make_float4(hstg[4 * 128 + tid], hstg[5 * 128 + tid],
                                              hstg[6 * 128 + tid], hstg[7 * 128 + tid]);
        }
        if (t + 1 < TSTEPS)
            LOAD_XP32(t + 1);

        // ---- gather (block 0, warp 0; 64 flags = lanes 0..15 x v4) + release ----
        if (bid == 0 && wid == 0) {
            const unsigned tgt = (unsigned)(t + 1);
            for (;;) {
                bool ok = true;
                if (lane < 16) {
                    unsigned f0, f1, f2, f3;
                    asm volatile("ld.volatile.global.v4.u32 {%0,%1,%2,%3}, [%4];"
                        : "=r"(f0), "=r"(f1), "=r"(f2), "=r"(f3)
                        : "l"(g_flags + lane * 4));
                    ok = (f0 >= tgt) & (f1 >= tgt) & (f2 >= tgt) & (f3 >= tgt);
                }
                if (__all_sync(0xffffffffu, ok)) break;
            }
            if (lane == 0) {
                __threadfence();
                *(volatile unsigned*)&g_genv = tgt;
            }
        }
        // ---- wait ----
        if (tid == 0) {
            while (*(volatile unsigned*)&g_genv < (unsigned)(t + 1)) { }
            __threadfence();
        }
        __syncthreads();
    }

    // final h, c
    {
        const size_t oh = (size_t)TSTEPS * BATCH * HID;
#pragma unroll
        for (int q = 0; q < 4; q++) {
            const int u = ug + q;
            out[oh + (size_t)b_ * HID + j0 + u]                       = hreg[q];
            out[oh + (size_t)BATCH * HID + (size_t)b_ * HID + j0 + u] = creg[q];
        }
    }
}

// ---------------------------------------------------------------------------
extern "C" void kernel_launch(void* const* d_in, const int* in_sizes, int n_in,
                              void* d_out, int out_size) {
    const float* x   = (const float*)d_in[0];
    const float* Wih = (const float*)d_in[1];
    const float* bih = (const float*)d_in[2];
    const float* Whh = (const float*)d_in[3];
    const float* bhh = (const float*)d_in[4];
    float* out = (float*)d_out;
    (void)in_sizes; (void)n_in; (void)out_size;

    split_x_kernel<<<4096, 256>>>(x);
    split_w_kernel<<<512, 256>>>(Wih);

    cudaFuncSetAttribute(xproj_mma_kernel,
                         cudaFuncAttributeMaxDynamicSharedMemorySize, SMEM_XP);
    dim3 g1(GATES / 128, TSTEPS);
    xproj_mma_kernel<<<g1, 256, SMEM_XP>>>(bih, bhh);

    cudaFuncSetAttribute(rec14_kernel,
                         cudaFuncAttributeMaxDynamicSharedMemorySize, SMEM_REC14);
    rec14_kernel<<<NBLK, 256, SMEM_REC14>>>(Whh, out);
}